// round 1
// baseline (speedup 1.0000x reference)
#include <cuda_runtime.h>
#include <math.h>
#include <stdint.h>

#define BB   32
#define NN   1024
#define DD   64
#define HH   128
#define OUTD 8
#define KK   16
#define CAP  160
#define NODES (BB*NN)

// ---------------- scratch (static device globals; no runtime alloc) ----------
__device__ float g_maskf[NODES];
__device__ float g_px[NODES];
__device__ float g_py[NODES];
__device__ float g_deg[NODES];
__device__ float g_dinv[NODES];
__device__ float g_coef[NODES];          // dinv * maskf  (source-side coefficient)
__device__ int   g_cnt[NODES];
__device__ int   g_nbr[NODES*KK];
__device__ int   g_rev[NODES*CAP];       // reverse adjacency (global source ids)
__device__ float g_y[NODES*HH];
__device__ float g_h[NODES*HH];

// ---------------- 1. mask / pos / deg init ----------------------------------
__global__ void prep_kernel(const float* __restrict__ obs) {
    int m = blockIdx.x * 256 + threadIdx.x;          // 0..32767
    const float4* row = (const float4*)(obs + m * DD);
    bool any = false;
    float x0 = 0.f, y0 = 0.f;
    #pragma unroll
    for (int i = 0; i < 16; i++) {
        float4 v = row[i];
        if (i == 0) { x0 = v.x; y0 = v.y; }
        any = any || (v.x != 0.f) || (v.y != 0.f) || (v.z != 0.f) || (v.w != 0.f);
    }
    float mf = any ? 1.f : 0.f;
    g_maskf[m] = mf;
    g_px[m] = x0;
    g_py[m] = y0;
    g_deg[m] = 2.f * mf;
    g_cnt[m] = 0;
}

// ---------------- 2. kNN top-(K+1), warp per node ----------------------------
// key = (bits(d2) << 32) | j : monotone in d2 (non-negative floats), ties break
// toward lower index j — exactly lax.top_k semantics. Invalid candidates get
// d2 = +inf by encoding masked positions as +inf.
__global__ void topk_kernel() {
    __shared__ float sx[NN], sy[NN];
    int b = blockIdx.y;
    for (int j = threadIdx.x; j < NN; j += 256) {
        float mf = g_maskf[b*NN + j];
        float X = g_px[b*NN + j], Y = g_py[b*NN + j];
        sx[j] = (mf != 0.f) ? X : __int_as_float(0x7F800000);
        sy[j] = (mf != 0.f) ? Y : __int_as_float(0x7F800000);
    }
    __syncthreads();

    int warp = threadIdx.x >> 5, lane = threadIdx.x & 31;
    int n = blockIdx.x * 8 + warp;
    float xn = sx[n], yn = sy[n];

    unsigned long long keys[32];
    #pragma unroll
    for (int i = 0; i < 32; i++) {
        int j = (i << 5) | lane;
        float dx = xn - sx[j];
        float dy = yn - sy[j];
        float d2 = __fadd_rn(__fmul_rn(dx, dx), __fmul_rn(dy, dy));
        keys[i] = ((unsigned long long)__float_as_uint(d2) << 32) | (unsigned)j;
    }

    unsigned sel = 0;
    unsigned long long lkey = ~0ull; int li = 0;
    #pragma unroll
    for (int i = 0; i < 32; i++)
        if (keys[i] < lkey) { lkey = keys[i]; li = i; }

    int out_base = (b*NN + n) * KK;
    for (int r = 0; r < KK + 1; r++) {
        unsigned long long w = lkey;
        #pragma unroll
        for (int s = 16; s >= 1; s >>= 1) {
            unsigned long long o = __shfl_xor_sync(0xffffffffu, w, s);
            if (o < w) w = o;
        }
        if (r > 0 && lane == 0)
            g_nbr[out_base + r - 1] = (int)(unsigned)(w & 0xffffffffull);
        if (w == lkey) {                       // unique owner (keys all distinct)
            sel |= (1u << li);
            lkey = ~0ull; li = 0;
            #pragma unroll
            for (int i = 0; i < 32; i++) {
                unsigned long long k2 = ((sel >> i) & 1u) ? ~0ull : keys[i];
                if (k2 < lkey) { lkey = k2; li = i; }
            }
        }
    }
}

// ---------------- 3. degree scatter + reverse adjacency ----------------------
__global__ void scatter_kernel() {
    int id = blockIdx.x * 256 + threadIdx.x;     // < NODES*KK
    int m = id >> 4;                             // global source node
    if (g_maskf[m] == 0.f) return;
    int t  = g_nbr[id];                          // local target in batch
    int gt = (m & ~(NN - 1)) + t;
    atomicAdd(&g_deg[gt], 1.0f);                 // exact integer adds
    int slot = atomicAdd(&g_cnt[gt], 1);
    if (slot < CAP) g_rev[gt * CAP + slot] = m;
}

// sort each reverse list -> deterministic gather accumulation order
__global__ void sortrev_kernel() {
    int m = blockIdx.x * 256 + threadIdx.x;
    int n = g_cnt[m]; if (n > CAP) n = CAP;
    int* r = &g_rev[m * CAP];
    for (int i = 1; i < n; i++) {
        int v = r[i]; int j = i - 1;
        while (j >= 0 && r[j] > v) { r[j+1] = r[j]; j--; }
        r[j+1] = v;
    }
}

__global__ void dinv_kernel() {
    int m = blockIdx.x * 256 + threadIdx.x;
    float d = g_deg[m];
    float di = d > 0.f ? (1.0f / sqrtf(d)) : 0.f;
    g_dinv[m] = di;
    g_coef[m] = di * g_maskf[m];
}

// ---------------- 4. GEMM: Y(32768xHH) = X(32768xDIN) @ W(DINxHH) ------------
template<int DIN>
__global__ __launch_bounds__(256) void gemm_kernel(const float* __restrict__ Xin,
                                                   const float* __restrict__ W) {
    const float* X = (DIN == DD) ? Xin : (const float*)g_h;
    __shared__ __align__(16) float Xs[32][64];     // [k][row]
    __shared__ __align__(16) float Ws[32][128];    // [k][col]
    int tid  = threadIdx.x;
    int lane = tid & 31;           // cols lane*4 .. +3
    int warp = tid >> 5;           // rows warp*8 .. +7
    int row0 = blockIdx.x * 64;

    float acc[8][4];
    #pragma unroll
    for (int r = 0; r < 8; r++)
        #pragma unroll
        for (int c = 0; c < 4; c++) acc[r][c] = 0.f;

    for (int kc = 0; kc < DIN; kc += 32) {
        #pragma unroll
        for (int t = 0; t < 2; t++) {              // X tile 64x32, transposed
            int f = tid + t * 256;                 // 0..511
            int r = f >> 3;
            int kq = (f & 7) << 2;
            float4 v = *(const float4*)(X + (row0 + r) * DIN + kc + kq);
            Xs[kq+0][r] = v.x; Xs[kq+1][r] = v.y;
            Xs[kq+2][r] = v.z; Xs[kq+3][r] = v.w;
        }
        #pragma unroll
        for (int t = 0; t < 4; t++) {              // W tile 32x128, direct
            int f = tid + t * 256;                 // 0..1023
            int k = f >> 5;
            int c = (f & 31) << 2;
            *(float4*)&Ws[k][c] = *(const float4*)(W + (kc + k) * HH + c);
        }
        __syncthreads();
        #pragma unroll
        for (int k = 0; k < 32; k++) {
            float4 a0 = *(const float4*)&Xs[k][warp*8];
            float4 a1 = *(const float4*)&Xs[k][warp*8 + 4];
            float4 bv = *(const float4*)&Ws[k][lane*4];
            float a[8] = {a0.x,a0.y,a0.z,a0.w,a1.x,a1.y,a1.z,a1.w};
            float bb[4] = {bv.x,bv.y,bv.z,bv.w};
            #pragma unroll
            for (int r = 0; r < 8; r++)
                #pragma unroll
                for (int c = 0; c < 4; c++)
                    acc[r][c] = fmaf(a[r], bb[c], acc[r][c]);
        }
        __syncthreads();
    }
    #pragma unroll
    for (int r = 0; r < 8; r++) {
        float4 v = {acc[r][0], acc[r][1], acc[r][2], acc[r][3]};
        *(float4*)(g_y + (row0 + warp*8 + r) * HH + lane*4) = v;
    }
}

// ---------------- 5. gather + self-term + tanh -------------------------------
// h[m] = tanh( dinv[m]*sum_{src in rev[m]} coef[src]*y[src] + 2*dinv[m]^2*y[m] + b )
__global__ void gather_kernel(const float* __restrict__ bias) {
    int m = blockIdx.x;
    int c = threadIdx.x;           // 0..127
    __shared__ int   ssrc[CAP];
    __shared__ float scf[CAP];
    int nsrc = g_cnt[m]; if (nsrc > CAP) nsrc = CAP;
    for (int s = c; s < nsrc; s += 128) {
        int src = g_rev[m * CAP + s];
        ssrc[s] = src;
        scf[s]  = g_coef[src];
    }
    __syncthreads();
    float agg = 0.f, agg2 = 0.f;
    int s = 0;
    for (; s + 1 < nsrc; s += 2) {
        agg  = fmaf(scf[s],     g_y[ssrc[s]     * HH + c], agg);
        agg2 = fmaf(scf[s + 1], g_y[ssrc[s + 1] * HH + c], agg2);
    }
    if (s < nsrc) agg = fmaf(scf[s], g_y[ssrc[s] * HH + c], agg);
    agg += agg2;
    float dm = g_dinv[m];
    float ym = g_y[m * HH + c];
    float v = dm * agg + 2.f * dm * dm * ym + bias[c];
    g_h[m * HH + c] = tanhf(v);
}

// ---------------- 6. output head: out = (h @ Wout + bout) * maskf ------------
__global__ void final_kernel(const float* __restrict__ Wout,
                             const float* __restrict__ bout,
                             float* __restrict__ out) {
    int tid = threadIdx.x;
    int lane = tid & 31, warp = tid >> 5;
    int m = blockIdx.x * 8 + warp;

    float wreg[32];                               // Wout rows lane*4..+3 (8 each)
    #pragma unroll
    for (int i = 0; i < 8; i++)
        *(float4*)&wreg[i*4] = *(const float4*)(Wout + lane * 32 + i * 4);

    float4 hv = *(const float4*)(g_h + m * HH + lane * 4);
    float hk[4] = {hv.x, hv.y, hv.z, hv.w};
    float acc[8];
    #pragma unroll
    for (int o = 0; o < 8; o++) acc[o] = 0.f;
    #pragma unroll
    for (int j = 0; j < 4; j++)
        #pragma unroll
        for (int o = 0; o < 8; o++)
            acc[o] = fmaf(hk[j], wreg[j*8 + o], acc[o]);
    #pragma unroll
    for (int o = 0; o < 8; o++)
        #pragma unroll
        for (int s = 16; s >= 1; s >>= 1)
            acc[o] += __shfl_xor_sync(0xffffffffu, acc[o], s);
    if (lane == 0) {
        float mf = g_maskf[m];
        #pragma unroll
        for (int o = 0; o < 8; o++)
            out[m * OUTD + o] = (acc[o] + bout[o]) * mf;
    }
}

// ---------------- launch ------------------------------------------------------
extern "C" void kernel_launch(void* const* d_in, const int* in_sizes, int n_in,
                              void* d_out, int out_size) {
    const float* obs  = (const float*)d_in[0];
    const float* W1   = (const float*)d_in[1];
    const float* b1   = (const float*)d_in[2];
    const float* W2   = (const float*)d_in[3];
    const float* b2   = (const float*)d_in[4];
    const float* Wout = (const float*)d_in[5];
    const float* bout = (const float*)d_in[6];
    float* out = (float*)d_out;

    prep_kernel   <<<NODES/256, 256>>>(obs);
    topk_kernel   <<<dim3(NN/8, BB), 256>>>();
    scatter_kernel<<<NODES*KK/256, 256>>>();
    sortrev_kernel<<<NODES/256, 256>>>();
    dinv_kernel   <<<NODES/256, 256>>>();

    gemm_kernel<DD><<<NODES/64, 256>>>(obs, W1);   // layer 1: obs @ W1 -> g_y
    gather_kernel <<<NODES, 128>>>(b1);            // -> g_h (tanh)
    gemm_kernel<HH><<<NODES/64, 256>>>(obs, W2);   // layer 2: g_h @ W2 -> g_y
    gather_kernel <<<NODES, 128>>>(b2);            // -> g_h (tanh)
    final_kernel  <<<NODES/8, 256>>>(Wout, bout, out);
}

// round 2
// speedup vs baseline: 1.9637x; 1.9637x over previous
#include <cuda_runtime.h>
#include <math.h>
#include <stdint.h>

#define BB   32
#define NN   1024
#define DD   64
#define HH   128
#define OUTD 8
#define KK   16
#define CAP  128
#define NODES (BB*NN)

// ---------------- scratch (static device globals; no runtime alloc) ----------
__device__ float    g_maskf[NODES];
__device__ float    g_px[NODES];
__device__ float    g_py[NODES];
__device__ float    g_dinv[NODES];
__device__ float    g_coef[NODES];           // dinv * maskf (source-side coefficient)
__device__ int      g_cnt[NODES];
__device__ int      g_nbr[NODES*KK];
__device__ unsigned g_mask[NODES*32];        // reverse adjacency bitmask (per target)
__device__ int      g_rev[NODES*CAP];        // reverse adjacency lists (sorted by construction)
__device__ float    g_y[NODES*HH];
__device__ float    g_h[NODES*HH];

// ---------------- 1. mask / pos init + zero bitmask ---------------------------
__global__ void prep_kernel(const float* __restrict__ obs) {
    int m = blockIdx.x * 256 + threadIdx.x;          // 0..32767
    const float4* row = (const float4*)(obs + m * DD);
    bool any = false;
    float x0 = 0.f, y0 = 0.f;
    #pragma unroll
    for (int i = 0; i < 16; i++) {
        float4 v = row[i];
        if (i == 0) { x0 = v.x; y0 = v.y; }
        any = any || (v.x != 0.f) || (v.y != 0.f) || (v.z != 0.f) || (v.w != 0.f);
    }
    float mf = any ? 1.f : 0.f;
    g_maskf[m] = mf;
    g_px[m] = x0;
    g_py[m] = y0;
    int4 z = {0,0,0,0};
    int4* mk = (int4*)&g_mask[m * 32];
    #pragma unroll
    for (int i = 0; i < 8; i++) mk[i] = z;
}

// ---------------- 2. kNN top-(K+1), warp per node, grouped rescan -------------
// key = (bits(d2) << 32) | j : monotone in d2 (non-negative), ties -> lower j,
// exactly lax.top_k semantics. Masked candidates get d2 = +inf.
#define U64MIN(a,b) (((a) < (b)) ? (a) : (b))
#define MSK(s)      ((((sel) >> (s)) & 1u) ? ~0ull : keys[s])
#define GRPMIN8(B, dst) do {                                   \
    unsigned long long a0 = U64MIN(MSK(B+0), MSK(B+1));        \
    unsigned long long a1 = U64MIN(MSK(B+2), MSK(B+3));        \
    unsigned long long a2 = U64MIN(MSK(B+4), MSK(B+5));        \
    unsigned long long a3 = U64MIN(MSK(B+6), MSK(B+7));        \
    dst = U64MIN(U64MIN(a0, a1), U64MIN(a2, a3));              \
} while (0)

__global__ __launch_bounds__(256) void topk_kernel() {
    __shared__ float sx[NN], sy[NN];
    int b = blockIdx.y;
    for (int j = threadIdx.x; j < NN; j += 256) {
        float mf = g_maskf[b*NN + j];
        float X = g_px[b*NN + j], Y = g_py[b*NN + j];
        float inf = __int_as_float(0x7F800000);
        sx[j] = (mf != 0.f) ? X : inf;
        sy[j] = (mf != 0.f) ? Y : inf;
    }
    __syncthreads();

    int warp = threadIdx.x >> 5, lane = threadIdx.x & 31;
    int n = blockIdx.x * 8 + warp;
    float xn = sx[n], yn = sy[n];

    unsigned long long keys[32];
    #pragma unroll
    for (int i = 0; i < 32; i++) {
        int j = (i << 5) | lane;
        float dx = xn - sx[j];
        float dy = yn - sy[j];
        float d2 = __fadd_rn(__fmul_rn(dx, dx), __fmul_rn(dy, dy));
        keys[i] = ((unsigned long long)__float_as_uint(d2) << 32) | (unsigned)j;
    }

    unsigned sel = 0;
    unsigned long long grp0, grp1, grp2, grp3;
    GRPMIN8(0,  grp0);
    GRPMIN8(8,  grp1);
    GRPMIN8(16, grp2);
    GRPMIN8(24, grp3);
    unsigned long long lkey = U64MIN(U64MIN(grp0, grp1), U64MIN(grp2, grp3));

    int out_base = (b*NN + n) * KK;
    #pragma unroll 1
    for (int r = 0; r < KK + 1; r++) {
        unsigned long long w = lkey;
        #pragma unroll
        for (int s = 16; s >= 1; s >>= 1) {
            unsigned long long o = __shfl_xor_sync(0xffffffffu, w, s);
            if (o < w) w = o;
        }
        if (r > 0 && lane == 0)
            g_nbr[out_base + r - 1] = (int)(unsigned)(w & 0xffffffffull);
        if (r < KK && w == lkey) {              // unique owner refills
            unsigned j = (unsigned)w & (NN - 1);
            int slot = j >> 5;
            sel |= (1u << slot);
            int g = slot >> 3;
            unsigned long long gm;
            if      (g == 0) { GRPMIN8(0,  gm); grp0 = gm; }
            else if (g == 1) { GRPMIN8(8,  gm); grp1 = gm; }
            else if (g == 2) { GRPMIN8(16, gm); grp2 = gm; }
            else             { GRPMIN8(24, gm); grp3 = gm; }
            lkey = U64MIN(U64MIN(grp0, grp1), U64MIN(grp2, grp3));
        }
    }
}

// ---------------- 3. edge scatter into target bitmasks ------------------------
__global__ void scatter_kernel() {
    int id = blockIdx.x * 256 + threadIdx.x;     // < NODES*KK
    int m = id >> 4;                             // global source node
    if (g_maskf[m] == 0.f) return;
    int t    = g_nbr[id];                        // local target in batch
    int gt   = (m & ~(NN - 1)) + t;
    int mloc = m & (NN - 1);
    atomicOr(&g_mask[gt * 32 + (mloc >> 5)], 1u << (mloc & 31));
}

// ---------------- 4. listify: bitmask -> sorted list + deg/dinv/coef ----------
__global__ void listify_kernel() {
    int lane = threadIdx.x & 31;
    int m = (blockIdx.x * 256 + threadIdx.x) >> 5;   // warp per node
    unsigned wbits = g_mask[m * 32 + lane];
    int c = __popc(wbits);
    int pre = c;                                     // inclusive scan of counts
    #pragma unroll
    for (int s = 1; s < 32; s <<= 1) {
        int nv = __shfl_up_sync(0xffffffffu, pre, s);
        if (lane >= s) pre += nv;
    }
    int total = __shfl_sync(0xffffffffu, pre, 31);
    int base  = pre - c;
    if (lane == 0) {
        float mf = g_maskf[m];
        float d  = (float)total + 2.f * mf;
        float di = d > 0.f ? (1.0f / sqrtf(d)) : 0.f;
        g_dinv[m] = di;
        g_coef[m] = di * mf;
        g_cnt[m]  = total < CAP ? total : CAP;
    }
    int gb = (m & ~(NN - 1)) + (lane << 5);          // global source id base for this word
    while (wbits) {
        int j = __ffs(wbits) - 1;
        wbits &= wbits - 1;
        if (base < CAP) g_rev[m * CAP + base] = gb + j;
        base++;
    }
}

// ---------------- 5. GEMM: Y(32768xHH) = X(32768xDIN) @ W(DINxHH) -------------
template<int DIN>
__global__ __launch_bounds__(256) void gemm_kernel(const float* __restrict__ Xin,
                                                   const float* __restrict__ W) {
    const float* X = (DIN == DD) ? Xin : (const float*)g_h;
    __shared__ __align__(16) float Xs[32][64];     // [k][row]
    __shared__ __align__(16) float Ws[32][128];    // [k][col]
    int tid  = threadIdx.x;
    int lane = tid & 31;           // cols lane*4 .. +3
    int warp = tid >> 5;           // rows warp*8 .. +7
    int row0 = blockIdx.x * 64;

    float acc[8][4];
    #pragma unroll
    for (int r = 0; r < 8; r++)
        #pragma unroll
        for (int c = 0; c < 4; c++) acc[r][c] = 0.f;

    for (int kc = 0; kc < DIN; kc += 32) {
        #pragma unroll
        for (int t = 0; t < 2; t++) {              // X tile 64x32, transposed
            int f = tid + t * 256;                 // 0..511
            int r = f >> 3;
            int kq = (f & 7) << 2;
            float4 v = *(const float4*)(X + (row0 + r) * DIN + kc + kq);
            Xs[kq+0][r] = v.x; Xs[kq+1][r] = v.y;
            Xs[kq+2][r] = v.z; Xs[kq+3][r] = v.w;
        }
        #pragma unroll
        for (int t = 0; t < 4; t++) {              // W tile 32x128, direct
            int f = tid + t * 256;                 // 0..1023
            int k = f >> 5;
            int c = (f & 31) << 2;
            *(float4*)&Ws[k][c] = *(const float4*)(W + (kc + k) * HH + c);
        }
        __syncthreads();
        #pragma unroll
        for (int k = 0; k < 32; k++) {
            float4 a0 = *(const float4*)&Xs[k][warp*8];
            float4 a1 = *(const float4*)&Xs[k][warp*8 + 4];
            float4 bv = *(const float4*)&Ws[k][lane*4];
            float a[8] = {a0.x,a0.y,a0.z,a0.w,a1.x,a1.y,a1.z,a1.w};
            float bb[4] = {bv.x,bv.y,bv.z,bv.w};
            #pragma unroll
            for (int r = 0; r < 8; r++)
                #pragma unroll
                for (int c = 0; c < 4; c++)
                    acc[r][c] = fmaf(a[r], bb[c], acc[r][c]);
        }
        __syncthreads();
    }
    #pragma unroll
    for (int r = 0; r < 8; r++) {
        float4 v = {acc[r][0], acc[r][1], acc[r][2], acc[r][3]};
        *(float4*)(g_y + (row0 + warp*8 + r) * HH + lane*4) = v;
    }
}

// ---------------- 6. gather + self-term + tanh --------------------------------
// h[m] = tanh( dinv[m]*sum_{src in rev[m]} coef[src]*y[src] + 2*dinv[m]^2*y[m] + b )
__global__ void gather_kernel(const float* __restrict__ bias) {
    int m = blockIdx.x;
    int c = threadIdx.x;           // 0..127
    __shared__ int   ssrc[CAP];
    __shared__ float scf[CAP];
    int nsrc = g_cnt[m];
    for (int s = c; s < nsrc; s += 128) {
        int src = g_rev[m * CAP + s];
        ssrc[s] = src;
        scf[s]  = g_coef[src];
    }
    __syncthreads();
    float agg = 0.f, agg2 = 0.f;
    int s = 0;
    for (; s + 1 < nsrc; s += 2) {
        agg  = fmaf(scf[s],     g_y[ssrc[s]     * HH + c], agg);
        agg2 = fmaf(scf[s + 1], g_y[ssrc[s + 1] * HH + c], agg2);
    }
    if (s < nsrc) agg = fmaf(scf[s], g_y[ssrc[s] * HH + c], agg);
    agg += agg2;
    float dm = g_dinv[m];
    float ym = g_y[m * HH + c];
    float v = dm * agg + 2.f * dm * dm * ym + bias[c];
    g_h[m * HH + c] = tanhf(v);
}

// ---------------- 7. output head: out = (h @ Wout + bout) * maskf -------------
__global__ void final_kernel(const float* __restrict__ Wout,
                             const float* __restrict__ bout,
                             float* __restrict__ out) {
    int tid = threadIdx.x;
    int lane = tid & 31, warp = tid >> 5;
    int m = blockIdx.x * 8 + warp;

    float wreg[32];                               // Wout rows lane*4..+3 (8 outs each)
    #pragma unroll
    for (int i = 0; i < 8; i++)
        *(float4*)&wreg[i*4] = *(const float4*)(Wout + lane * 32 + i * 4);

    float4 hv = *(const float4*)(g_h + m * HH + lane * 4);
    float hk[4] = {hv.x, hv.y, hv.z, hv.w};
    float acc[8];
    #pragma unroll
    for (int o = 0; o < 8; o++) acc[o] = 0.f;
    #pragma unroll
    for (int j = 0; j < 4; j++)
        #pragma unroll
        for (int o = 0; o < 8; o++)
            acc[o] = fmaf(hk[j], wreg[j*8 + o], acc[o]);
    #pragma unroll
    for (int o = 0; o < 8; o++)
        #pragma unroll
        for (int s = 16; s >= 1; s >>= 1)
            acc[o] += __shfl_xor_sync(0xffffffffu, acc[o], s);
    if (lane == 0) {
        float mf = g_maskf[m];
        #pragma unroll
        for (int o = 0; o < 8; o++)
            out[m * OUTD + o] = (acc[o] + bout[o]) * mf;
    }
}

// ---------------- launch ------------------------------------------------------
extern "C" void kernel_launch(void* const* d_in, const int* in_sizes, int n_in,
                              void* d_out, int out_size) {
    const float* obs  = (const float*)d_in[0];
    const float* W1   = (const float*)d_in[1];
    const float* b1   = (const float*)d_in[2];
    const float* W2   = (const float*)d_in[3];
    const float* b2   = (const float*)d_in[4];
    const float* Wout = (const float*)d_in[5];
    const float* bout = (const float*)d_in[6];
    float* out = (float*)d_out;

    prep_kernel   <<<NODES/256, 256>>>(obs);
    topk_kernel   <<<dim3(NN/8, BB), 256>>>();
    scatter_kernel<<<NODES*KK/256, 256>>>();
    listify_kernel<<<NODES/8, 256>>>();

    gemm_kernel<DD><<<NODES/64, 256>>>(obs, W1);   // layer 1: obs @ W1 -> g_y
    gather_kernel <<<NODES, 128>>>(b1);            // -> g_h (tanh)
    gemm_kernel<HH><<<NODES/64, 256>>>(obs, W2);   // layer 2: g_h @ W2 -> g_y
    gather_kernel <<<NODES, 128>>>(b2);            // -> g_h (tanh)
    final_kernel  <<<NODES/8, 256>>>(Wout, bout, out);
}

// round 6
// speedup vs baseline: 2.2654x; 1.1537x over previous
#include <cuda_runtime.h>
#include <math.h>
#include <stdint.h>

#define BB   32
#define NN   1024
#define DD   64
#define HH   128
#define OUTD 8
#define KK   16
#define CAP  128
#define NODES (BB*NN)

// ---------------- scratch (static device globals; no runtime alloc) ----------
__device__ float    g_maskf[NODES];
__device__ float    g_px[NODES];
__device__ float    g_py[NODES];
__device__ float    g_dinv[NODES];
__device__ float    g_coef[NODES];           // dinv * maskf (source-side coefficient)
__device__ int      g_cnt[NODES];
__device__ int      g_nbr[NODES*KK];
__device__ unsigned g_mask[NODES*32];        // reverse adjacency bitmask (per target)
__device__ int      g_rev[NODES*CAP];        // reverse adjacency lists (sorted by construction)
__device__ float    g_a[NODES*HH];           // pregather output (GEMM input)
__device__ float    g_h[NODES*HH];           // layer activations

// ---------------- 1. mask / pos init + zero bitmask ---------------------------
__global__ void prep_kernel(const float* __restrict__ obs) {
    int m = blockIdx.x * 256 + threadIdx.x;          // 0..32767
    const float4* row = (const float4*)(obs + m * DD);
    bool any = false;
    float x0 = 0.f, y0 = 0.f;
    #pragma unroll
    for (int i = 0; i < 16; i++) {
        float4 v = row[i];
        if (i == 0) { x0 = v.x; y0 = v.y; }
        any = any || (v.x != 0.f) || (v.y != 0.f) || (v.z != 0.f) || (v.w != 0.f);
    }
    float mf = any ? 1.f : 0.f;
    g_maskf[m] = mf;
    g_px[m] = x0;
    g_py[m] = y0;
    int4 z = {0,0,0,0};
    int4* mk = (int4*)&g_mask[m * 32];
    #pragma unroll
    for (int i = 0; i < 8; i++) mk[i] = z;
}

// ---------------- 2. kNN top-(K+1), warp per node (R2-proven code) ------------
// key = (bits(d2) << 32) | j : monotone in d2 (non-negative), ties -> lower j,
// exactly lax.top_k semantics. Masked candidates get d2 = +inf.
#define U64MIN(a,b) (((a) < (b)) ? (a) : (b))
#define MSK(s)      ((((sel) >> (s)) & 1u) ? ~0ull : keys[s])
#define GRPMIN8(B, dst) do {                                   \
    unsigned long long a0 = U64MIN(MSK(B+0), MSK(B+1));        \
    unsigned long long a1 = U64MIN(MSK(B+2), MSK(B+3));        \
    unsigned long long a2 = U64MIN(MSK(B+4), MSK(B+5));        \
    unsigned long long a3 = U64MIN(MSK(B+6), MSK(B+7));        \
    dst = U64MIN(U64MIN(a0, a1), U64MIN(a2, a3));              \
} while (0)

__global__ __launch_bounds__(256) void topk_kernel() {
    __shared__ float sx[NN], sy[NN];
    int b = blockIdx.y;
    for (int j = threadIdx.x; j < NN; j += 256) {
        float mf = g_maskf[b*NN + j];
        float X = g_px[b*NN + j], Y = g_py[b*NN + j];
        float inf = __int_as_float(0x7F800000);
        sx[j] = (mf != 0.f) ? X : inf;
        sy[j] = (mf != 0.f) ? Y : inf;
    }
    __syncthreads();

    int warp = threadIdx.x >> 5, lane = threadIdx.x & 31;
    int n = blockIdx.x * 8 + warp;
    float xn = sx[n], yn = sy[n];

    unsigned long long keys[32];
    #pragma unroll
    for (int i = 0; i < 32; i++) {
        int j = (i << 5) | lane;
        float dx = xn - sx[j];
        float dy = yn - sy[j];
        float d2 = __fadd_rn(__fmul_rn(dx, dx), __fmul_rn(dy, dy));
        keys[i] = ((unsigned long long)__float_as_uint(d2) << 32) | (unsigned)j;
    }

    unsigned sel = 0;
    unsigned long long grp0, grp1, grp2, grp3;
    GRPMIN8(0,  grp0);
    GRPMIN8(8,  grp1);
    GRPMIN8(16, grp2);
    GRPMIN8(24, grp3);
    unsigned long long lkey = U64MIN(U64MIN(grp0, grp1), U64MIN(grp2, grp3));

    int out_base = (b*NN + n) * KK;
    #pragma unroll 1
    for (int r = 0; r < KK + 1; r++) {
        unsigned long long w = lkey;
        #pragma unroll
        for (int s = 16; s >= 1; s >>= 1) {
            unsigned long long o = __shfl_xor_sync(0xffffffffu, w, s);
            if (o < w) w = o;
        }
        if (r > 0 && lane == 0)
            g_nbr[out_base + r - 1] = (int)(unsigned)(w & 0xffffffffull);
        if (r < KK && w == lkey) {              // unique owner (keys distinct) refills
            unsigned j = (unsigned)w & (NN - 1);
            int slot = j >> 5;
            sel |= (1u << slot);
            int g = slot >> 3;
            unsigned long long gm;
            if      (g == 0) { GRPMIN8(0,  gm); grp0 = gm; }
            else if (g == 1) { GRPMIN8(8,  gm); grp1 = gm; }
            else if (g == 2) { GRPMIN8(16, gm); grp2 = gm; }
            else             { GRPMIN8(24, gm); grp3 = gm; }
            lkey = U64MIN(U64MIN(grp0, grp1), U64MIN(grp2, grp3));
        }
    }
}

// ---------------- 3. edge scatter into target bitmasks ------------------------
__global__ void scatter_kernel() {
    int id = blockIdx.x * 256 + threadIdx.x;     // < NODES*KK
    int m = id >> 4;                             // global source node
    if (g_maskf[m] == 0.f) return;
    int t    = g_nbr[id];                        // local target in batch
    int gt   = (m & ~(NN - 1)) + t;
    int mloc = m & (NN - 1);
    atomicOr(&g_mask[gt * 32 + (mloc >> 5)], 1u << (mloc & 31));
}

// ---------------- 4. listify: bitmask -> sorted list + deg/dinv/coef ----------
__global__ void listify_kernel() {
    int lane = threadIdx.x & 31;
    int m = (blockIdx.x * 256 + threadIdx.x) >> 5;   // warp per node
    unsigned wbits = g_mask[m * 32 + lane];
    int c = __popc(wbits);
    int pre = c;                                     // inclusive scan of counts
    #pragma unroll
    for (int s = 1; s < 32; s <<= 1) {
        int nv = __shfl_up_sync(0xffffffffu, pre, s);
        if (lane >= s) pre += nv;
    }
    int total = __shfl_sync(0xffffffffu, pre, 31);
    int base  = pre - c;
    if (lane == 0) {
        float mf = g_maskf[m];
        float d  = (float)total + 2.f * mf;
        float di = d > 0.f ? (1.0f / sqrtf(d)) : 0.f;
        g_dinv[m] = di;
        g_coef[m] = di * mf;
        g_cnt[m]  = total < CAP ? total : CAP;
    }
    int gb = (m & ~(NN - 1)) + (lane << 5);          // global source id base for this word
    while (wbits) {
        int j = __ffs(wbits) - 1;
        wbits &= wbits - 1;
        if (base < CAP) g_rev[m * CAP + base] = gb + j;
        base++;
    }
}

// ---------------- 5. pregather (linearity: aggregate BEFORE the GEMM) ---------
// g_a[m] = dinv[m] * sum_{src} coef[src]*X[src] + 2*dinv[m]^2 * X[m]
// FROMOBS selects the source INSIDE the kernel (no __device__ symbol crosses
// the host launch boundary).
template<int DIN, bool FROMOBS>
__global__ void pregather_kernel(const float* __restrict__ obs) {
    const float* X = FROMOBS ? obs : (const float*)g_h;
    constexpr int NPB = 128 / DIN;                   // nodes per block
    int local = threadIdx.x / DIN;
    int c     = threadIdx.x % DIN;
    int m = blockIdx.x * NPB + local;
    __shared__ int   ssrc[NPB][CAP];
    __shared__ float scf[NPB][CAP];
    int nsrc = g_cnt[m];
    for (int s = c; s < nsrc; s += DIN) {
        int src = g_rev[m * CAP + s];
        ssrc[local][s] = src;
        scf[local][s]  = g_coef[src];
    }
    __syncthreads();
    float agg = 0.f, agg2 = 0.f;
    int s = 0;
    for (; s + 1 < nsrc; s += 2) {
        agg  = fmaf(scf[local][s],     X[ssrc[local][s]     * DIN + c], agg);
        agg2 = fmaf(scf[local][s + 1], X[ssrc[local][s + 1] * DIN + c], agg2);
    }
    if (s < nsrc) agg = fmaf(scf[local][s], X[ssrc[local][s] * DIN + c], agg);
    agg += agg2;
    float dm = g_dinv[m];
    float xm = X[m * DIN + c];
    g_a[m * DIN + c] = dm * agg + 2.f * dm * dm * xm;
}

// ---------------- 6. GEMM + bias + tanh (+ optional fused output head) --------
// Reads g_a directly; H(64x128 per block) = tanh( g_a @ W + b ).
// If FINAL: out = (H @ Wout + bout) * maskf from SMEM-staged H; else H -> g_h.
#define XS(k,r) smem_f[(k)*64 + (r)]
#define WS(k,c) smem_f[2048 + (k)*128 + (c)]
#define HS(r,c) smem_f[(r)*128 + (c)]

template<int DIN, bool FINAL>
__global__ __launch_bounds__(256) void gemm_kernel(const float* __restrict__ W,
                                                   const float* __restrict__ bias,
                                                   const float* __restrict__ Wout,
                                                   const float* __restrict__ bout,
                                                   float* __restrict__ out) {
    const float* X = (const float*)g_a;
    __shared__ __align__(16) float smem_f[8192];
    int tid  = threadIdx.x;
    int lane = tid & 31;           // cols lane*4 .. +3
    int warp = tid >> 5;           // rows warp*8 .. +7
    int row0 = blockIdx.x * 64;

    float4 bv = *(const float4*)(bias + lane * 4);

    float acc[8][4];
    #pragma unroll
    for (int r = 0; r < 8; r++)
        #pragma unroll
        for (int c = 0; c < 4; c++) acc[r][c] = 0.f;

    for (int kc = 0; kc < DIN; kc += 32) {
        #pragma unroll
        for (int t = 0; t < 2; t++) {              // X tile 64x32, transposed
            int f = tid + t * 256;                 // 0..511
            int r = f >> 3;
            int kq = (f & 7) << 2;
            float4 v = *(const float4*)(X + (row0 + r) * DIN + kc + kq);
            XS(kq+0, r) = v.x; XS(kq+1, r) = v.y;
            XS(kq+2, r) = v.z; XS(kq+3, r) = v.w;
        }
        #pragma unroll
        for (int t = 0; t < 4; t++) {              // W tile 32x128, direct
            int f = tid + t * 256;                 // 0..1023
            int k = f >> 5;
            int c = (f & 31) << 2;
            *(float4*)&WS(k, c) = *(const float4*)(W + (kc + k) * HH + c);
        }
        __syncthreads();
        #pragma unroll
        for (int k = 0; k < 32; k++) {
            float4 a0 = *(const float4*)&XS(k, warp*8);
            float4 a1 = *(const float4*)&XS(k, warp*8 + 4);
            float4 wv = *(const float4*)&WS(k, lane*4);
            float a[8] = {a0.x,a0.y,a0.z,a0.w,a1.x,a1.y,a1.z,a1.w};
            float bb[4] = {wv.x,wv.y,wv.z,wv.w};
            #pragma unroll
            for (int r = 0; r < 8; r++)
                #pragma unroll
                for (int c = 0; c < 4; c++)
                    acc[r][c] = fmaf(a[r], bb[c], acc[r][c]);
        }
        __syncthreads();
    }

    if (!FINAL) {
        #pragma unroll
        for (int r = 0; r < 8; r++) {
            float4 v;
            v.x = tanhf(acc[r][0] + bv.x);
            v.y = tanhf(acc[r][1] + bv.y);
            v.z = tanhf(acc[r][2] + bv.z);
            v.w = tanhf(acc[r][3] + bv.w);
            *(float4*)(g_h + (row0 + warp*8 + r) * HH + lane*4) = v;
        }
    } else {
        // stage tanh'd tile in SMEM, then per-warp 8x8 head matvec
        #pragma unroll
        for (int r = 0; r < 8; r++) {
            float4 v;
            v.x = tanhf(acc[r][0] + bv.x);
            v.y = tanhf(acc[r][1] + bv.y);
            v.z = tanhf(acc[r][2] + bv.z);
            v.w = tanhf(acc[r][3] + bv.w);
            *(float4*)&HS(warp*8 + r, lane*4) = v;
        }
        __syncthreads();
        float wreg[32];                           // Wout rows lane*4..+3 (8 outs each)
        #pragma unroll
        for (int i = 0; i < 8; i++)
            *(float4*)&wreg[i*4] = *(const float4*)(Wout + lane * 32 + i * 4);
        #pragma unroll
        for (int rr = 0; rr < 8; rr++) {
            int row = warp * 8 + rr;
            float4 hv = *(const float4*)&HS(row, lane*4);
            float hk[4] = {hv.x, hv.y, hv.z, hv.w};
            float a2[8];
            #pragma unroll
            for (int o = 0; o < 8; o++) a2[o] = 0.f;
            #pragma unroll
            for (int j = 0; j < 4; j++)
                #pragma unroll
                for (int o = 0; o < 8; o++)
                    a2[o] = fmaf(hk[j], wreg[j*8 + o], a2[o]);
            #pragma unroll
            for (int o = 0; o < 8; o++)
                #pragma unroll
                for (int s = 16; s >= 1; s >>= 1)
                    a2[o] += __shfl_xor_sync(0xffffffffu, a2[o], s);
            if (lane == 0) {
                int m = row0 + row;
                float mf = g_maskf[m];
                #pragma unroll
                for (int o = 0; o < 8; o++)
                    out[m * OUTD + o] = (a2[o] + bout[o]) * mf;
            }
        }
    }
}

// ---------------- launch ------------------------------------------------------
extern "C" void kernel_launch(void* const* d_in, const int* in_sizes, int n_in,
                              void* d_out, int out_size) {
    const float* obs  = (const float*)d_in[0];
    const float* W1   = (const float*)d_in[1];
    const float* b1   = (const float*)d_in[2];
    const float* W2   = (const float*)d_in[3];
    const float* b2   = (const float*)d_in[4];
    const float* Wout = (const float*)d_in[5];
    const float* bout = (const float*)d_in[6];
    float* out = (float*)d_out;

    prep_kernel   <<<NODES/256, 256>>>(obs);
    topk_kernel   <<<dim3(NN/8, BB), 256>>>();
    scatter_kernel<<<NODES*KK/256, 256>>>();
    listify_kernel<<<NODES/8, 256>>>();

    pregather_kernel<DD, true> <<<NODES/2, 128>>>(obs);              // 64-dim gather -> g_a
    gemm_kernel<DD, false><<<NODES/64, 256>>>(W1, b1, 0, 0, 0);      // g_a @ W1 -> g_h (tanh)
    pregather_kernel<HH, false><<<NODES, 128>>>(obs);                // 128-dim gather g_h -> g_a
    gemm_kernel<HH, true><<<NODES/64, 256>>>(W2, b2, Wout, bout, out); // -> out
}

// round 7
// speedup vs baseline: 2.5625x; 1.1311x over previous
#include <cuda_runtime.h>
#include <math.h>
#include <stdint.h>

#define BB   32
#define NN   1024
#define DD   64
#define HH   128
#define OUTD 8
#define KK   16
#define CAP  128
#define NODES (BB*NN)

// ---------------- scratch (static device globals; no runtime alloc) ----------
__device__ float    g_maskf[NODES];
__device__ float    g_px[NODES];
__device__ float    g_py[NODES];
__device__ float    g_dinv[NODES];
__device__ float    g_coef[NODES];           // dinv * maskf (source-side coefficient)
__device__ int      g_cnt[NODES];
__device__ int      g_nbr[NODES*KK];
__device__ unsigned g_mask[NODES*32];        // reverse adjacency bitmask (per target)
__device__ int      g_rev[NODES*CAP];        // reverse adjacency lists (sorted by construction)
__device__ float    g_a[NODES*HH];           // pregather output (GEMM input)
__device__ float    g_h[NODES*HH];           // layer activations

// ---------------- 1. mask / pos init + zero bitmask ---------------------------
__global__ void prep_kernel(const float* __restrict__ obs) {
    int m = blockIdx.x * 256 + threadIdx.x;          // 0..32767
    const float4* row = (const float4*)(obs + m * DD);
    bool any = false;
    float x0 = 0.f, y0 = 0.f;
    #pragma unroll
    for (int i = 0; i < 16; i++) {
        float4 v = row[i];
        if (i == 0) { x0 = v.x; y0 = v.y; }
        any = any || (v.x != 0.f) || (v.y != 0.f) || (v.z != 0.f) || (v.w != 0.f);
    }
    float mf = any ? 1.f : 0.f;
    g_maskf[m] = mf;
    g_px[m] = x0;
    g_py[m] = y0;
    int4 z = {0,0,0,0};
    int4* mk = (int4*)&g_mask[m * 32];
    #pragma unroll
    for (int i = 0; i < 8; i++) mk[i] = z;
}

// ---------------- 2. kNN top-(K+1), warp per node, 32-bit keys ----------------
// Per lane: 32 d2 values as raw fp32 bits (non-negative floats: bit order ==
// numeric order; NaN bits sort last). Global index j = (slot<<5)|lane is
// recomputed, never stored. Tie-break: among lanes holding the min bits, the
// min of (lslot<<5)|lane is exactly the min j  ->  identical ordering to the
// old u64 (bits<<32)|j scheme, i.e. exact lax.top_k semantics.
#define REGRP(G, DM, DS) do {                                    \
    unsigned bm = 0xFFFFFFFFu; int bs = 0;                       \
    _Pragma("unroll")                                            \
    for (int s = (G)*8; s < (G)*8 + 8; s++) {                    \
        bool ok = (((sel >> s) & 1u) == 0u) && (u[s] < bm);      \
        bm = ok ? u[s] : bm;                                     \
        bs = ok ? s    : bs;                                     \
    }                                                            \
    DM = bm; DS = bs;                                            \
} while (0)

__global__ __launch_bounds__(256) void topk_kernel() {
    __shared__ float sx[NN], sy[NN];
    int b = blockIdx.y;
    for (int j = threadIdx.x; j < NN; j += 256) {
        float mf = g_maskf[b*NN + j];
        float X = g_px[b*NN + j], Y = g_py[b*NN + j];
        float inf = __int_as_float(0x7F800000);
        sx[j] = (mf != 0.f) ? X : inf;
        sy[j] = (mf != 0.f) ? Y : inf;
    }
    __syncthreads();

    int warp = threadIdx.x >> 5, lane = threadIdx.x & 31;
    int n = blockIdx.x * 8 + warp;
    float xn = sx[n], yn = sy[n];

    unsigned u[32];
    #pragma unroll
    for (int i = 0; i < 32; i++) {
        int j = (i << 5) | lane;
        float dx = xn - sx[j];
        float dy = yn - sy[j];
        float d2 = __fadd_rn(__fmul_rn(dx, dx), __fmul_rn(dy, dy));
        u[i] = __float_as_uint(d2);
    }

    unsigned sel = 0;
    unsigned gm0, gm1, gm2, gm3;
    int      gs0, gs1, gs2, gs3;
    REGRP(0, gm0, gs0);
    REGRP(1, gm1, gs1);
    REGRP(2, gm2, gs2);
    REGRP(3, gm3, gs3);
    unsigned lmin = gm0; int lslot = gs0;              // ascending groups + strict <
    if (gm1 < lmin) { lmin = gm1; lslot = gs1; }       //   => lowest slot on ties
    if (gm2 < lmin) { lmin = gm2; lslot = gs2; }
    if (gm3 < lmin) { lmin = gm3; lslot = gs3; }

    int out_base = (b*NN + n) * KK;
    #pragma unroll 1
    for (int r = 0; r < KK + 1; r++) {
        // phase 1: warp-min of d2 bits
        unsigned w = lmin;
        #pragma unroll
        for (int s = 16; s >= 1; s >>= 1) {
            unsigned o = __shfl_xor_sync(0xffffffffu, w, s);
            w = o < w ? o : w;
        }
        // phase 2: among tied lanes, min j = (lslot<<5)|lane
        int cand = (lmin == w) ? ((lslot << 5) | lane) : 0x7FFFFFFF;
        #pragma unroll
        for (int s = 16; s >= 1; s >>= 1) {
            int o = __shfl_xor_sync(0xffffffffu, cand, s);
            cand = o < cand ? o : cand;
        }
        int jwin = cand;                               // uniform across warp
        if (r > 0 && lane == 0)
            g_nbr[out_base + r - 1] = jwin;
        if (r < KK && lane == (jwin & 31)) {           // owner refills
            int slot = jwin >> 5;
            sel |= (1u << slot);
            int g = slot >> 3;
            if      (g == 0) REGRP(0, gm0, gs0);
            else if (g == 1) REGRP(1, gm1, gs1);
            else if (g == 2) REGRP(2, gm2, gs2);
            else             REGRP(3, gm3, gs3);
            lmin = gm0; lslot = gs0;
            if (gm1 < lmin) { lmin = gm1; lslot = gs1; }
            if (gm2 < lmin) { lmin = gm2; lslot = gs2; }
            if (gm3 < lmin) { lmin = gm3; lslot = gs3; }
        }
    }
}

// ---------------- 3. edge scatter into target bitmasks ------------------------
__global__ void scatter_kernel() {
    int id = blockIdx.x * 256 + threadIdx.x;     // < NODES*KK
    int m = id >> 4;                             // global source node
    if (g_maskf[m] == 0.f) return;
    int t    = g_nbr[id];                        // local target in batch
    int gt   = (m & ~(NN - 1)) + t;
    int mloc = m & (NN - 1);
    atomicOr(&g_mask[gt * 32 + (mloc >> 5)], 1u << (mloc & 31));
}

// ---------------- 4. listify: bitmask -> sorted list + deg/dinv/coef ----------
__global__ void listify_kernel() {
    int lane = threadIdx.x & 31;
    int m = (blockIdx.x * 256 + threadIdx.x) >> 5;   // warp per node
    unsigned wbits = g_mask[m * 32 + lane];
    int c = __popc(wbits);
    int pre = c;                                     // inclusive scan of counts
    #pragma unroll
    for (int s = 1; s < 32; s <<= 1) {
        int nv = __shfl_up_sync(0xffffffffu, pre, s);
        if (lane >= s) pre += nv;
    }
    int total = __shfl_sync(0xffffffffu, pre, 31);
    int base  = pre - c;
    if (lane == 0) {
        float mf = g_maskf[m];
        float d  = (float)total + 2.f * mf;
        float di = d > 0.f ? (1.0f / sqrtf(d)) : 0.f;
        g_dinv[m] = di;
        g_coef[m] = di * mf;
        g_cnt[m]  = total < CAP ? total : CAP;
    }
    int gb = (m & ~(NN - 1)) + (lane << 5);          // global source id base for this word
    while (wbits) {
        int j = __ffs(wbits) - 1;
        wbits &= wbits - 1;
        if (base < CAP) g_rev[m * CAP + base] = gb + j;
        base++;
    }
}

// ---------------- 5. pregather (linearity: aggregate BEFORE the GEMM) ---------
// g_a[m] = dinv[m] * sum_{src} coef[src]*X[src] + 2*dinv[m]^2 * X[m]
template<int DIN, bool FROMOBS>
__global__ void pregather_kernel(const float* __restrict__ obs) {
    const float* X = FROMOBS ? obs : (const float*)g_h;
    constexpr int NPB = 128 / DIN;                   // nodes per block
    int local = threadIdx.x / DIN;
    int c     = threadIdx.x % DIN;
    int m = blockIdx.x * NPB + local;
    __shared__ int   ssrc[NPB][CAP];
    __shared__ float scf[NPB][CAP];
    int nsrc = g_cnt[m];
    for (int s = c; s < nsrc; s += DIN) {
        int src = g_rev[m * CAP + s];
        ssrc[local][s] = src;
        scf[local][s]  = g_coef[src];
    }
    __syncthreads();
    float agg = 0.f, agg2 = 0.f;
    int s = 0;
    for (; s + 1 < nsrc; s += 2) {
        agg  = fmaf(scf[local][s],     X[ssrc[local][s]     * DIN + c], agg);
        agg2 = fmaf(scf[local][s + 1], X[ssrc[local][s + 1] * DIN + c], agg2);
    }
    if (s < nsrc) agg = fmaf(scf[local][s], X[ssrc[local][s] * DIN + c], agg);
    agg += agg2;
    float dm = g_dinv[m];
    float xm = X[m * DIN + c];
    g_a[m * DIN + c] = dm * agg + 2.f * dm * dm * xm;
}

// ---------------- 6. GEMM + bias + tanh (+ optional fused output head) --------
#define XS(k,r) smem_f[(k)*64 + (r)]
#define WS(k,c) smem_f[2048 + (k)*128 + (c)]
#define HS(r,c) smem_f[(r)*128 + (c)]

template<int DIN, bool FINAL>
__global__ __launch_bounds__(256) void gemm_kernel(const float* __restrict__ W,
                                                   const float* __restrict__ bias,
                                                   const float* __restrict__ Wout,
                                                   const float* __restrict__ bout,
                                                   float* __restrict__ out) {
    const float* X = (const float*)g_a;
    __shared__ __align__(16) float smem_f[8192];
    int tid  = threadIdx.x;
    int lane = tid & 31;           // cols lane*4 .. +3
    int warp = tid >> 5;           // rows warp*8 .. +7
    int row0 = blockIdx.x * 64;

    float4 bv = *(const float4*)(bias + lane * 4);

    float acc[8][4];
    #pragma unroll
    for (int r = 0; r < 8; r++)
        #pragma unroll
        for (int c = 0; c < 4; c++) acc[r][c] = 0.f;

    for (int kc = 0; kc < DIN; kc += 32) {
        #pragma unroll
        for (int t = 0; t < 2; t++) {              // X tile 64x32, transposed
            int f = tid + t * 256;                 // 0..511
            int r = f >> 3;
            int kq = (f & 7) << 2;
            float4 v = *(const float4*)(X + (row0 + r) * DIN + kc + kq);
            XS(kq+0, r) = v.x; XS(kq+1, r) = v.y;
            XS(kq+2, r) = v.z; XS(kq+3, r) = v.w;
        }
        #pragma unroll
        for (int t = 0; t < 4; t++) {              // W tile 32x128, direct
            int f = tid + t * 256;                 // 0..1023
            int k = f >> 5;
            int c = (f & 31) << 2;
            *(float4*)&WS(k, c) = *(const float4*)(W + (kc + k) * HH + c);
        }
        __syncthreads();
        #pragma unroll
        for (int k = 0; k < 32; k++) {
            float4 a0 = *(const float4*)&XS(k, warp*8);
            float4 a1 = *(const float4*)&XS(k, warp*8 + 4);
            float4 wv = *(const float4*)&WS(k, lane*4);
            float a[8] = {a0.x,a0.y,a0.z,a0.w,a1.x,a1.y,a1.z,a1.w};
            float bb[4] = {wv.x,wv.y,wv.z,wv.w};
            #pragma unroll
            for (int r = 0; r < 8; r++)
                #pragma unroll
                for (int c = 0; c < 4; c++)
                    acc[r][c] = fmaf(a[r], bb[c], acc[r][c]);
        }
        __syncthreads();
    }

    if (!FINAL) {
        #pragma unroll
        for (int r = 0; r < 8; r++) {
            float4 v;
            v.x = tanhf(acc[r][0] + bv.x);
            v.y = tanhf(acc[r][1] + bv.y);
            v.z = tanhf(acc[r][2] + bv.z);
            v.w = tanhf(acc[r][3] + bv.w);
            *(float4*)(g_h + (row0 + warp*8 + r) * HH + lane*4) = v;
        }
    } else {
        #pragma unroll
        for (int r = 0; r < 8; r++) {
            float4 v;
            v.x = tanhf(acc[r][0] + bv.x);
            v.y = tanhf(acc[r][1] + bv.y);
            v.z = tanhf(acc[r][2] + bv.z);
            v.w = tanhf(acc[r][3] + bv.w);
            *(float4*)&HS(warp*8 + r, lane*4) = v;
        }
        __syncthreads();
        float wreg[32];                           // Wout rows lane*4..+3 (8 outs each)
        #pragma unroll
        for (int i = 0; i < 8; i++)
            *(float4*)&wreg[i*4] = *(const float4*)(Wout + lane * 32 + i * 4);
        #pragma unroll
        for (int rr = 0; rr < 8; rr++) {
            int row = warp * 8 + rr;
            float4 hv = *(const float4*)&HS(row, lane*4);
            float hk[4] = {hv.x, hv.y, hv.z, hv.w};
            float a2[8];
            #pragma unroll
            for (int o = 0; o < 8; o++) a2[o] = 0.f;
            #pragma unroll
            for (int j = 0; j < 4; j++)
                #pragma unroll
                for (int o = 0; o < 8; o++)
                    a2[o] = fmaf(hk[j], wreg[j*8 + o], a2[o]);
            #pragma unroll
            for (int o = 0; o < 8; o++)
                #pragma unroll
                for (int s = 16; s >= 1; s >>= 1)
                    a2[o] += __shfl_xor_sync(0xffffffffu, a2[o], s);
            if (lane == 0) {
                int m = row0 + row;
                float mf = g_maskf[m];
                #pragma unroll
                for (int o = 0; o < 8; o++)
                    out[m * OUTD + o] = (a2[o] + bout[o]) * mf;
            }
        }
    }
}

// ---------------- launch ------------------------------------------------------
extern "C" void kernel_launch(void* const* d_in, const int* in_sizes, int n_in,
                              void* d_out, int out_size) {
    const float* obs  = (const float*)d_in[0];
    const float* W1   = (const float*)d_in[1];
    const float* b1   = (const float*)d_in[2];
    const float* W2   = (const float*)d_in[3];
    const float* b2   = (const float*)d_in[4];
    const float* Wout = (const float*)d_in[5];
    const float* bout = (const float*)d_in[6];
    float* out = (float*)d_out;

    prep_kernel   <<<NODES/256, 256>>>(obs);
    topk_kernel   <<<dim3(NN/8, BB), 256>>>();
    scatter_kernel<<<NODES*KK/256, 256>>>();
    listify_kernel<<<NODES/8, 256>>>();

    pregather_kernel<DD, true> <<<NODES/2, 128>>>(obs);              // 64-dim gather -> g_a
    gemm_kernel<DD, false><<<NODES/64, 256>>>(W1, b1, 0, 0, 0);      // g_a @ W1 -> g_h (tanh)
    pregather_kernel<HH, false><<<NODES, 128>>>(obs);                // 128-dim gather g_h -> g_a
    gemm_kernel<HH, true><<<NODES/64, 256>>>(W2, b2, Wout, bout, out); // -> out
}